// round 9
// baseline (speedup 1.0000x reference)
#include <cuda_runtime.h>
#include <cuda_fp16.h>
#include <math.h>
#include <stdint.h>

// Problem dims
#define BN 16
#define SN 512
#define DM 256
#define HN 8
#define DKN 32
#define DVN 32
#define CTXW 288   // DV*(H+1)

// ---------------- scratch (device globals; no allocation allowed) ----------------
__device__ float g_Qp[BN*SN*DM];          // [b,s,h*32+d]
__device__ float g_Kp[BN*SN*DM];
__device__ float g_Vp[BN*SN*DM];
__device__ float g_V2p[BN*SN*DVN];        // [b,s,32]
__device__ __half g_attnH[BN*HN*SN*SN];   // [b,h,q,k]  fp16 (67MB)
__device__ float g_ctx[BN*SN*CTXW];       // [b,s,288]
__device__ int   g_mask_mode;             // 0=u8, 1=i32, 2=f32

// ---------------- mask dtype detection ----------------
__global__ void detect_mask_kernel(const unsigned int* __restrict__ m) {
    __shared__ int f32flag, bigflag;
    if (threadIdx.x == 0) { f32flag = 0; bigflag = 0; }
    __syncthreads();
    int lf = 0, lb = 0;
    for (int i = threadIdx.x; i < 8192; i += 256) {
        unsigned int w = m[i];
        if (w == 0x3F800000u) lf = 1;
        else if (w > 1u) lb = 1;
    }
    if (lf) atomicOr(&f32flag, 1);
    if (lb) atomicOr(&bigflag, 1);
    __syncthreads();
    if (threadIdx.x == 0)
        g_mask_mode = f32flag ? 2 : (bigflag ? 0 : 1);
}

// ---------------- fused QKV projection: 3 GEMMs in one launch, double-buffered ----
__global__ void __launch_bounds__(256) qkv_kernel(
    const float* __restrict__ Aq, const float* __restrict__ Ak, const float* __restrict__ Av,
    const float* __restrict__ Wq, const float* __restrict__ Wk, const float* __restrict__ Wv,
    float* __restrict__ Cq, float* __restrict__ Ck, float* __restrict__ Cv)
{
    const float* __restrict__ A;
    const float* __restrict__ W;
    float* __restrict__ C;
    if (blockIdx.z == 0)      { A = Aq; W = Wq; C = Cq; }
    else if (blockIdx.z == 1) { A = Ak; W = Wk; C = Ck; }
    else                      { A = Av; W = Wv; C = Cv; }

    __shared__ float As[2][128 * 20];   // [m][k] padded to 20
    __shared__ float Bs[2][16 * 128];   // [k][n]

    int tid = threadIdx.x;
    int row0 = blockIdx.y * 128, col0 = blockIdx.x * 128;
    int tr = (tid >> 4) * 4, tc = (tid & 15) * 4;

    float acc[8][8];
    #pragma unroll
    for (int i = 0; i < 8; i++)
        #pragma unroll
        for (int j = 0; j < 8; j++) acc[i][j] = 0.f;

    float4 pa[2], pb[2];
    #pragma unroll
    for (int t = 0; t < 2; t++) {
        int lin = tid + t * 256;
        pa[t] = *(const float4*)&A[(size_t)(row0 + (lin >> 2)) * DM + (lin & 3) * 4];
        pb[t] = *(const float4*)&W[(size_t)(lin >> 5) * DM + col0 + (lin & 31) * 4];
    }
    #pragma unroll
    for (int t = 0; t < 2; t++) {
        int lin = tid + t * 256;
        *(float4*)&As[0][(lin >> 2) * 20 + (lin & 3) * 4] = pa[t];
        *(float4*)&Bs[0][(lin >> 5) * 128 + (lin & 31) * 4] = pb[t];
    }
    __syncthreads();

    const int NT = DM / 16;
    for (int kt = 0; kt < NT; kt++) {
        int cur = kt & 1;
        if (kt + 1 < NT) {
            int k0 = (kt + 1) * 16;
            #pragma unroll
            for (int t = 0; t < 2; t++) {
                int lin = tid + t * 256;
                pa[t] = *(const float4*)&A[(size_t)(row0 + (lin >> 2)) * DM + k0 + (lin & 3) * 4];
                pb[t] = *(const float4*)&W[(size_t)(k0 + (lin >> 5)) * DM + col0 + (lin & 31) * 4];
            }
        }
        #pragma unroll
        for (int kk = 0; kk < 16; kk++) {
            float ar[8], br[8];
            #pragma unroll
            for (int i = 0; i < 4; i++) {
                ar[i]     = As[cur][(tr + i) * 20 + kk];
                ar[4 + i] = As[cur][(tr + 64 + i) * 20 + kk];
            }
            *(float4*)&br[0] = *(const float4*)&Bs[cur][kk * 128 + tc];
            *(float4*)&br[4] = *(const float4*)&Bs[cur][kk * 128 + tc + 64];
            #pragma unroll
            for (int i = 0; i < 8; i++)
                #pragma unroll
                for (int j = 0; j < 8; j++)
                    acc[i][j] += ar[i] * br[j];
        }
        if (kt + 1 < NT) {
            int nxt = cur ^ 1;
            #pragma unroll
            for (int t = 0; t < 2; t++) {
                int lin = tid + t * 256;
                *(float4*)&As[nxt][(lin >> 2) * 20 + (lin & 3) * 4] = pa[t];
                *(float4*)&Bs[nxt][(lin >> 5) * 128 + (lin & 31) * 4] = pb[t];
            }
        }
        __syncthreads();
    }
    #pragma unroll
    for (int ih = 0; ih < 2; ih++)
        #pragma unroll
        for (int i = 0; i < 4; i++) {
            int row = row0 + tr + ih * 64 + i;
            #pragma unroll
            for (int jh = 0; jh < 2; jh++) {
                float4 v = make_float4(acc[ih*4+i][jh*4+0], acc[ih*4+i][jh*4+1],
                                       acc[ih*4+i][jh*4+2], acc[ih*4+i][jh*4+3]);
                *(float4*)&C[(size_t)row * DM + col0 + tc + jh * 64] = v;
            }
        }
}

// ---------------- skinny GEMM: V2p = input_V @ W_V2 ----------------
__global__ void __launch_bounds__(256) v2_kernel(
    const float* __restrict__ A, const float* __restrict__ W)
{
    int tid = threadIdx.x;
    int r = blockIdx.x * 8 + (tid >> 5);
    int c = tid & 31;
    const float* ar = A + (size_t)r * DM;
    float acc = 0.f;
    #pragma unroll 8
    for (int k = 0; k < DM; k++)
        acc += ar[k] * W[k * 32 + c];
    g_V2p[r * 32 + c] = acc;
}

// ---------------- fused attention ----------------
// grid (S/64, H, B), 512 threads.
// smem: sS[64*512] + sKV[512*36] + sQ[64*36] = 214016 B
__global__ void __launch_bounds__(512) attn_kernel(const void* __restrict__ mask)
{
    extern __shared__ float sh[];
    float* sS  = sh;                 // 64 x 512  (also reused as 16x2048 partials)
    float* sKV = sh + 64 * 512;      // 512 x 36  (K, then V)
    float* sQ  = sKV + 512 * 36;     // 64 x 36

    int tid = threadIdx.x;
    int q0 = blockIdx.x * 64, h = blockIdx.y, b = blockIdx.z;
    int mode = g_mask_mode;

    // load Q tile (64x32) as float4 (512 float4, one per thread)
    {
        int qq = tid >> 3, d4 = (tid & 7) * 4;
        *(float4*)&sQ[qq * 36 + d4] =
            *(const float4*)&g_Qp[((b * SN + q0 + qq) * DM) + h * 32 + d4];
    }
    // load K (512x32) as float4
    #pragma unroll
    for (int t = 0; t < 8; t++) {
        int lin = tid + t * 512;
        int kk = lin >> 3, d4 = (lin & 7) * 4;
        *(float4*)&sKV[kk * 36 + d4] =
            *(const float4*)&g_Kp[((b * SN + kk) * DM) + h * 32 + d4];
    }
    __syncthreads();

    const float scale = 0.17677669529663687f; // 1/sqrt(32)
    int qg = tid >> 6;   // 0..7 : 8 q-rows each
    int kl = tid & 63;   // k columns kl + j*64

    float acc[8][8];
    #pragma unroll
    for (int i = 0; i < 8; i++)
        #pragma unroll
        for (int j = 0; j < 8; j++) acc[i][j] = 0.f;

    #pragma unroll
    for (int d = 0; d < 32; d += 4) {
        float4 qv[8];
        #pragma unroll
        for (int i = 0; i < 8; i++) qv[i] = *(const float4*)&sQ[(qg * 8 + i) * 36 + d];
        #pragma unroll
        for (int j = 0; j < 8; j++) {
            float4 kv = *(const float4*)&sKV[(kl + j * 64) * 36 + d];
            #pragma unroll
            for (int i = 0; i < 8; i++) {
                acc[i][j] += qv[i].x * kv.x;
                acc[i][j] += qv[i].y * kv.y;
                acc[i][j] += qv[i].z * kv.z;
                acc[i][j] += qv[i].w * kv.w;
            }
        }
    }

    int mrow0 = ((b * HN + h) * SN + q0) * SN;
    #pragma unroll
    for (int i = 0; i < 8; i++) {
        int q = qg * 8 + i;
        #pragma unroll
        for (int j = 0; j < 8; j++) {
            int k = kl + j * 64;
            int midx = mrow0 + q * SN + k;
            bool msk;
            if (mode == 0)      msk = ((const unsigned char*)mask)[midx] != 0;
            else if (mode == 1) msk = ((const int*)mask)[midx] != 0;
            else                msk = ((const float*)mask)[midx] != 0.0f;
            sS[q * 512 + k] = msk ? -1e9f : acc[i][j] * scale;
        }
    }
    __syncthreads();

    // reload sKV with V (512x32) — K no longer needed
    #pragma unroll
    for (int t = 0; t < 8; t++) {
        int lin = tid + t * 512;
        int kk = lin >> 3, d4 = (lin & 7) * 4;
        *(float4*)&sKV[kk * 36 + d4] =
            *(const float4*)&g_Vp[((b * SN + kk) * DM) + h * 32 + d4];
    }

    // exact softmax per row (16 warps x 4 rows), emit fp16 attn map
    int warp = tid >> 5, lane = tid & 31;
    #pragma unroll
    for (int rep = 0; rep < 4; rep++) {
        int r = warp * 4 + rep;
        float mx = -INFINITY;
        #pragma unroll
        for (int i = 0; i < 16; i++) mx = fmaxf(mx, sS[r * 512 + lane + i * 32]);
        #pragma unroll
        for (int o = 16; o; o >>= 1) mx = fmaxf(mx, __shfl_xor_sync(0xffffffffu, mx, o));
        float sum = 0.f;
        #pragma unroll
        for (int i = 0; i < 16; i++) {
            int c = lane + i * 32;
            float p = __expf(sS[r * 512 + c] - mx);
            sS[r * 512 + c] = p; sum += p;
        }
        #pragma unroll
        for (int o = 16; o; o >>= 1) sum += __shfl_xor_sync(0xffffffffu, sum, o);
        float inv = 1.0f / sum;
        __syncwarp();
        size_t base = (size_t)(((b * HN + h) * SN + q0 + r)) * SN;
        #pragma unroll
        for (int i = 0; i < 8; i++) {
            int c0 = lane * 2 + i * 64;
            float2 pv = *(float2*)&sS[r * 512 + c0];
            pv.x *= inv; pv.y *= inv;
            *(float2*)&sS[r * 512 + c0] = pv;
            *(__half2*)&g_attnH[base + c0] = __floats2half2_rn(pv.x, pv.y);
        }
    }
    __syncthreads();

    // context = P @ V : 16-way k-split, each thread 8q x 8v over 32 k
    int part = tid >> 5;          // 0..15
    int pos  = tid & 31;
    int qi = pos >> 2;            // 0..7 -> q rows qi*8+i
    int vj = pos & 3;             // 0..3 -> v cols vj*8+j
    float cacc[8][8];
    #pragma unroll
    for (int i = 0; i < 8; i++)
        #pragma unroll
        for (int j = 0; j < 8; j++) cacc[i][j] = 0.f;

    #pragma unroll
    for (int kc = 0; kc < 8; kc++) {
        int k0 = part * 32 + kc * 4;
        float4 pv4[8];
        #pragma unroll
        for (int i = 0; i < 8; i++)
            pv4[i] = *(const float4*)&sS[(qi * 8 + i) * 512 + k0];
        #pragma unroll
        for (int m = 0; m < 4; m++) {
            float4 va = *(const float4*)&sKV[(k0 + m) * 36 + vj * 8];
            float4 vb = *(const float4*)&sKV[(k0 + m) * 36 + vj * 8 + 4];
            #pragma unroll
            for (int i = 0; i < 8; i++) {
                float p = (m == 0) ? pv4[i].x : (m == 1) ? pv4[i].y : (m == 2) ? pv4[i].z : pv4[i].w;
                cacc[i][0] += p * va.x; cacc[i][1] += p * va.y;
                cacc[i][2] += p * va.z; cacc[i][3] += p * va.w;
                cacc[i][4] += p * vb.x; cacc[i][5] += p * vb.y;
                cacc[i][6] += p * vb.z; cacc[i][7] += p * vb.w;
            }
        }
    }
    __syncthreads();   // all P reads complete; sS reusable as partial buffer
    #pragma unroll
    for (int i = 0; i < 8; i++) {
        int o = part * 2048 + (qi * 8 + i) * 32 + vj * 8;
        *(float4*)&sS[o]     = make_float4(cacc[i][0], cacc[i][1], cacc[i][2], cacc[i][3]);
        *(float4*)&sS[o + 4] = make_float4(cacc[i][4], cacc[i][5], cacc[i][6], cacc[i][7]);
    }
    __syncthreads();
    {
        int o = tid * 4;
        float4 s = make_float4(0.f, 0.f, 0.f, 0.f);
        #pragma unroll
        for (int p = 0; p < 16; p++) {
            float4 pp = *(const float4*)&sS[p * 2048 + o];
            s.x += pp.x; s.y += pp.y; s.z += pp.z; s.w += pp.w;
        }
        int q = o >> 5, dv = o & 31;
        *(float4*)&g_ctx[(b * SN + q0 + q) * CTXW + h * 32 + dv] = s;
    }
}

// ---------------- context2 = matrix @ V2p, per batch ----------------
__global__ void __launch_bounds__(256) ctx2_kernel(const float* __restrict__ matrix)
{
    __shared__ float Ms[128][33];
    __shared__ float Vs[32][33];
    int tid = threadIdx.x;
    int r0 = blockIdx.x * 128, b = blockIdx.y;
    int cg = tid & 7, rg = tid >> 3;
    float acc[4][4];
    #pragma unroll
    for (int i = 0; i < 4; i++)
        #pragma unroll
        for (int j = 0; j < 4; j++) acc[i][j] = 0.f;

    for (int kt = 0; kt < 16; kt++) {
        int k0 = kt * 32;
        #pragma unroll
        for (int t = 0; t < 16; t++) {
            int idx = tid + t * 256; int rr = idx >> 5, kk = idx & 31;
            Ms[rr][kk] = matrix[(size_t)(b * SN + r0 + rr) * SN + k0 + kk];
        }
        #pragma unroll
        for (int t = 0; t < 4; t++) {
            int idx = tid + t * 256; int kk = idx >> 5, c = idx & 31;
            Vs[kk][c] = g_V2p[(b * SN + k0 + kk) * 32 + c];
        }
        __syncthreads();
        #pragma unroll 8
        for (int kk = 0; kk < 32; kk++) {
            float a[4], w[4];
            #pragma unroll
            for (int i = 0; i < 4; i++) a[i] = Ms[rg * 4 + i][kk];
            #pragma unroll
            for (int j = 0; j < 4; j++) w[j] = Vs[kk][cg * 4 + j];
            #pragma unroll
            for (int i = 0; i < 4; i++)
                #pragma unroll
                for (int j = 0; j < 4; j++)
                    acc[i][j] += a[i] * w[j];
        }
        __syncthreads();
    }
    #pragma unroll
    for (int i = 0; i < 4; i++)
        #pragma unroll
        for (int j = 0; j < 4; j++)
            g_ctx[(b * SN + r0 + rg * 4 + i) * CTXW + 256 + cg * 4 + j] = acc[i][j];
}

// ---------------- gate MLP + matrix_out (attn in fp16) ----------------
__global__ void __launch_bounds__(256) gate_kernel(
    const float* __restrict__ matrix,
    const float* __restrict__ fug, const float* __restrict__ fub,
    const float* __restrict__ w1, const float* __restrict__ b1,
    const float* __restrict__ w2, const float* __restrict__ b2,
    float* __restrict__ out)
{
    __shared__ float As[8][32][33];
    __shared__ float Mt[32][33];
    __shared__ float sw1[54], sb1[6], sw2[6], sg[9], sbv[9];
    __shared__ float sb2;
    int tid = threadIdx.x;
    int x0 = blockIdx.x * 32, y0 = blockIdx.y * 32, b = blockIdx.z;

    if (tid < 54) sw1[tid] = w1[tid];
    else if (tid < 60) sb1[tid - 54] = b1[tid - 54];
    else if (tid < 66) sw2[tid - 60] = w2[tid - 60];
    else if (tid < 75) sg[tid - 66]  = fug[tid - 66];
    else if (tid < 84) sbv[tid - 75] = fub[tid - 75];
    else if (tid == 84) sb2 = b2[0];

    #pragma unroll
    for (int h = 0; h < 8; h++)
        #pragma unroll
        for (int t = 0; t < 2; t++) {
            int idx = tid + t * 256;         // 0..511
            int yy = idx >> 4, xp = idx & 15;
            __half2 hv = *(const __half2*)&g_attnH[
                (size_t)((b * 8 + h) * SN + y0 + yy) * SN + x0 + xp * 2];
            float2 fv = __half22float2(hv);
            As[h][yy][xp * 2]     = fv.x;
            As[h][yy][xp * 2 + 1] = fv.y;
        }
    #pragma unroll
    for (int t = 0; t < 4; t++) {
        int idx = tid + t * 256; int yy = idx >> 5, xx = idx & 31;
        Mt[yy][xx] = matrix[(size_t)(b * SN + y0 + yy) * SN + x0 + xx];
    }
    __syncthreads();

    #pragma unroll
    for (int t = 0; t < 4; t++) {
        int idx = tid + t * 256; int xx = idx >> 5, yy = idx & 31;
        float v[9];
        v[0] = Mt[yy][xx];
        #pragma unroll
        for (int h = 0; h < 8; h++) v[1 + h] = As[h][yy][xx];
        float s = 0.f, ss = 0.f;
        #pragma unroll
        for (int c = 0; c < 9; c++) { s += v[c]; ss += v[c] * v[c]; }
        float mean = s * (1.0f / 9.0f);
        float var = ss * (1.0f / 9.0f) - mean * mean;
        float inv = rsqrtf(var + 1e-5f);
        float h1[6];
        #pragma unroll
        for (int j = 0; j < 6; j++) h1[j] = sb1[j];
        #pragma unroll
        for (int c = 0; c < 9; c++) {
            float xn = sg[c] * ((v[c] - mean) * inv) + sbv[c];
            #pragma unroll
            for (int j = 0; j < 6; j++) h1[j] += xn * sw1[c * 6 + j];
        }
        float z = sb2;
        #pragma unroll
        for (int j = 0; j < 6; j++) z += fmaxf(h1[j], 0.f) * sw2[j];
        float gval = 1.0f / (1.0f + __expf(-z));
        size_t oidx = (size_t)(b * SN + x0 + xx) * SN + y0 + yy;
        out[oidx] = matrix[oidx] * gval;
    }
}

// ---------------- final: out = LN(ctx[8192x288] @ Wfc[288x256]) ----------------
__global__ void __launch_bounds__(256) final_kernel(
    const float* __restrict__ Wfc,
    const float* __restrict__ lng, const float* __restrict__ lnb,
    float* __restrict__ out)
{
    __shared__ float sW[32 * 256];
    __shared__ float As[16][33];
    int tid = threadIdx.x;
    int row0 = blockIdx.x * 16;
    int tx = tid & 63, ty = tid >> 6;
    float acc[4][4];
    #pragma unroll
    for (int i = 0; i < 4; i++)
        #pragma unroll
        for (int j = 0; j < 4; j++) acc[i][j] = 0.f;

    for (int k0 = 0; k0 < CTXW; k0 += 32) {
        #pragma unroll
        for (int t = 0; t < 32; t++) {
            int idx = tid + t * 256;
            sW[idx] = Wfc[(size_t)(k0 + (idx >> 8)) * 256 + (idx & 255)];
        }
        #pragma unroll
        for (int t = 0; t < 2; t++) {
            int idx = tid + t * 256; int rr = idx >> 5, kk = idx & 31;
            As[rr][kk] = g_ctx[(size_t)(row0 + rr) * CTXW + k0 + kk];
        }
        __syncthreads();
        #pragma unroll 8
        for (int kk = 0; kk < 32; kk++) {
            float a[4], w[4];
            #pragma unroll
            for (int i = 0; i < 4; i++) a[i] = As[ty * 4 + i][kk];
            #pragma unroll
            for (int j = 0; j < 4; j++) w[j] = sW[kk * 256 + tx + 64 * j];
            #pragma unroll
            for (int i = 0; i < 4; i++)
                #pragma unroll
                for (int j = 0; j < 4; j++)
                    acc[i][j] += a[i] * w[j];
        }
        __syncthreads();
    }
    #pragma unroll
    for (int i = 0; i < 4; i++)
        #pragma unroll
        for (int j = 0; j < 4; j++)
            sW[(ty * 4 + i) * 256 + tx + 64 * j] = acc[i][j];
    __syncthreads();

    int warp = tid >> 5, lane = tid & 31;
    #pragma unroll
    for (int rep = 0; rep < 2; rep++) {
        int r = warp * 2 + rep;
        float s = 0.f, ss = 0.f;
        #pragma unroll
        for (int i = 0; i < 8; i++) {
            float v = sW[r * 256 + lane + i * 32];
            s += v; ss += v * v;
        }
        #pragma unroll
        for (int o = 16; o; o >>= 1) {
            s  += __shfl_xor_sync(0xffffffffu, s, o);
            ss += __shfl_xor_sync(0xffffffffu, ss, o);
        }
        float mean = s * (1.f / 256.f);
        float var = ss * (1.f / 256.f) - mean * mean;
        float inv = rsqrtf(var + 1e-5f);
        #pragma unroll
        for (int i = 0; i < 8; i++) {
            int c = lane + i * 32;
            float v = sW[r * 256 + c];
            out[(size_t)(row0 + r) * 256 + c] = lng[c] * ((v - mean) * inv) + lnb[c];
        }
    }
}

// ---------------- launch ----------------
extern "C" void kernel_launch(void* const* d_in, const int* in_sizes, int n_in,
                              void* d_out, int out_size)
{
    const float* inQ   = (const float*)d_in[0];
    const float* inK   = (const float*)d_in[1];
    const float* inV   = (const float*)d_in[2];
    const void*  mask  = d_in[3];
    const float* matrix= (const float*)d_in[4];
    const float* WQ    = (const float*)d_in[5];
    const float* WK    = (const float*)d_in[6];
    const float* WV    = (const float*)d_in[7];
    const float* WV2   = (const float*)d_in[8];
    const float* Wfc   = (const float*)d_in[9];
    const float* lng   = (const float*)d_in[10];
    const float* lnb   = (const float*)d_in[11];
    const float* fug   = (const float*)d_in[12];
    const float* fub   = (const float*)d_in[13];
    const float* w1    = (const float*)d_in[14];
    const float* b1    = (const float*)d_in[15];
    const float* w2    = (const float*)d_in[16];
    const float* b2    = (const float*)d_in[17];
    float* out = (float*)d_out;

    float *Qp, *Kp, *Vp;
    cudaGetSymbolAddress((void**)&Qp, g_Qp);
    cudaGetSymbolAddress((void**)&Kp, g_Kp);
    cudaGetSymbolAddress((void**)&Vp, g_Vp);

    const int ATTN_SMEM = (64 * 512 + 512 * 36 + 64 * 36) * 4; // 214016 B
    cudaFuncSetAttribute(attn_kernel, cudaFuncAttributeMaxDynamicSharedMemorySize, ATTN_SMEM);

    detect_mask_kernel<<<1, 256>>>((const unsigned int*)mask);

    qkv_kernel<<<dim3(2, 64, 3), 256>>>(inQ, inK, inV, WQ, WK, WV, Qp, Kp, Vp);
    v2_kernel<<<BN * SN / 8, 256>>>(inV, WV2);

    attn_kernel<<<dim3(SN / 64, HN, BN), 512, ATTN_SMEM>>>(mask);

    ctx2_kernel<<<dim3(SN / 128, BN), 256>>>(matrix);

    gate_kernel<<<dim3(SN / 32, SN / 32, BN), 256>>>(
        matrix, fug, fub, w1, b1, w2, b2, out + (size_t)BN * SN * DM);

    final_kernel<<<BN * SN / 16, 256>>>(Wfc, lng, lnb, out);
}

// round 10
// speedup vs baseline: 1.0012x; 1.0012x over previous
#include <cuda_runtime.h>
#include <cuda_fp16.h>
#include <math.h>
#include <stdint.h>

// Problem dims
#define BN 16
#define SN 512
#define DM 256
#define HN 8
#define DKN 32
#define DVN 32
#define CTXW 288   // DV*(H+1)

// ---------------- scratch (device globals; no allocation allowed) ----------------
__device__ float g_Qp[BN*SN*DM];          // [b,s,h*32+d]
__device__ float g_Kp[BN*SN*DM];
__device__ float g_Vp[BN*SN*DM];
__device__ float g_V2p[BN*SN*DVN];        // [b,s,32]
__device__ __half g_attnH[BN*HN*SN*SN];   // [b,h,q,k]  fp16 (67MB)
__device__ float g_ctx[BN*SN*CTXW];       // [b,s,288]
__device__ int   g_mask_mode;             // 0=u8, 1=i32, 2=f32

// ---------------- mask dtype detection ----------------
__global__ void detect_mask_kernel(const unsigned int* __restrict__ m) {
    __shared__ int f32flag, bigflag;
    if (threadIdx.x == 0) { f32flag = 0; bigflag = 0; }
    __syncthreads();
    int lf = 0, lb = 0;
    for (int i = threadIdx.x; i < 8192; i += 256) {
        unsigned int w = m[i];
        if (w == 0x3F800000u) lf = 1;
        else if (w > 1u) lb = 1;
    }
    if (lf) atomicOr(&f32flag, 1);
    if (lb) atomicOr(&bigflag, 1);
    __syncthreads();
    if (threadIdx.x == 0)
        g_mask_mode = f32flag ? 2 : (bigflag ? 0 : 1);
}

// ---------------- fused QKV projection: 3 GEMMs in one launch, double-buffered ----
__global__ void __launch_bounds__(256) qkv_kernel(
    const float* __restrict__ Aq, const float* __restrict__ Ak, const float* __restrict__ Av,
    const float* __restrict__ Wq, const float* __restrict__ Wk, const float* __restrict__ Wv,
    float* __restrict__ Cq, float* __restrict__ Ck, float* __restrict__ Cv)
{
    const float* __restrict__ A;
    const float* __restrict__ W;
    float* __restrict__ C;
    if (blockIdx.z == 0)      { A = Aq; W = Wq; C = Cq; }
    else if (blockIdx.z == 1) { A = Ak; W = Wk; C = Ck; }
    else                      { A = Av; W = Wv; C = Cv; }

    __shared__ float As[2][128 * 20];   // [m][k] padded to 20
    __shared__ float Bs[2][16 * 128];   // [k][n]

    int tid = threadIdx.x;
    int row0 = blockIdx.y * 128, col0 = blockIdx.x * 128;
    int tr = (tid >> 4) * 4, tc = (tid & 15) * 4;

    float acc[8][8];
    #pragma unroll
    for (int i = 0; i < 8; i++)
        #pragma unroll
        for (int j = 0; j < 8; j++) acc[i][j] = 0.f;

    float4 pa[2], pb[2];
    #pragma unroll
    for (int t = 0; t < 2; t++) {
        int lin = tid + t * 256;
        pa[t] = *(const float4*)&A[(size_t)(row0 + (lin >> 2)) * DM + (lin & 3) * 4];
        pb[t] = *(const float4*)&W[(size_t)(lin >> 5) * DM + col0 + (lin & 31) * 4];
    }
    #pragma unroll
    for (int t = 0; t < 2; t++) {
        int lin = tid + t * 256;
        *(float4*)&As[0][(lin >> 2) * 20 + (lin & 3) * 4] = pa[t];
        *(float4*)&Bs[0][(lin >> 5) * 128 + (lin & 31) * 4] = pb[t];
    }
    __syncthreads();

    const int NT = DM / 16;
    for (int kt = 0; kt < NT; kt++) {
        int cur = kt & 1;
        if (kt + 1 < NT) {
            int k0 = (kt + 1) * 16;
            #pragma unroll
            for (int t = 0; t < 2; t++) {
                int lin = tid + t * 256;
                pa[t] = *(const float4*)&A[(size_t)(row0 + (lin >> 2)) * DM + k0 + (lin & 3) * 4];
                pb[t] = *(const float4*)&W[(size_t)(k0 + (lin >> 5)) * DM + col0 + (lin & 31) * 4];
            }
        }
        #pragma unroll
        for (int kk = 0; kk < 16; kk++) {
            float ar[8], br[8];
            #pragma unroll
            for (int i = 0; i < 4; i++) {
                ar[i]     = As[cur][(tr + i) * 20 + kk];
                ar[4 + i] = As[cur][(tr + 64 + i) * 20 + kk];
            }
            *(float4*)&br[0] = *(const float4*)&Bs[cur][kk * 128 + tc];
            *(float4*)&br[4] = *(const float4*)&Bs[cur][kk * 128 + tc + 64];
            #pragma unroll
            for (int i = 0; i < 8; i++)
                #pragma unroll
                for (int j = 0; j < 8; j++)
                    acc[i][j] += ar[i] * br[j];
        }
        if (kt + 1 < NT) {
            int nxt = cur ^ 1;
            #pragma unroll
            for (int t = 0; t < 2; t++) {
                int lin = tid + t * 256;
                *(float4*)&As[nxt][(lin >> 2) * 20 + (lin & 3) * 4] = pa[t];
                *(float4*)&Bs[nxt][(lin >> 5) * 128 + (lin & 31) * 4] = pb[t];
            }
        }
        __syncthreads();
    }
    #pragma unroll
    for (int ih = 0; ih < 2; ih++)
        #pragma unroll
        for (int i = 0; i < 4; i++) {
            int row = row0 + tr + ih * 64 + i;
            #pragma unroll
            for (int jh = 0; jh < 2; jh++) {
                float4 v = make_float4(acc[ih*4+i][jh*4+0], acc[ih*4+i][jh*4+1],
                                       acc[ih*4+i][jh*4+2], acc[ih*4+i][jh*4+3]);
                *(float4*)&C[(size_t)row * DM + col0 + tc + jh * 64] = v;
            }
        }
}

// ---------------- skinny GEMM: V2p = input_V @ W_V2 ----------------
__global__ void __launch_bounds__(256) v2_kernel(
    const float* __restrict__ A, const float* __restrict__ W)
{
    int tid = threadIdx.x;
    int r = blockIdx.x * 8 + (tid >> 5);
    int c = tid & 31;
    const float* ar = A + (size_t)r * DM;
    float acc = 0.f;
    #pragma unroll 8
    for (int k = 0; k < DM; k++)
        acc += ar[k] * W[k * 32 + c];
    g_V2p[r * 32 + c] = acc;
}

// ---------------- fused attention ----------------
// grid (S/64, H, B), 512 threads.
// smem: sS[64*512] + sKV[512*36] + sQ[64*36] = 214016 B
__global__ void __launch_bounds__(512) attn_kernel(const void* __restrict__ mask)
{
    extern __shared__ float sh[];
    float* sS  = sh;                 // 64 x 512  (also reused as 16x2048 partials)
    float* sKV = sh + 64 * 512;      // 512 x 36  (K, then V)
    float* sQ  = sKV + 512 * 36;     // 64 x 36

    int tid = threadIdx.x;
    int q0 = blockIdx.x * 64, h = blockIdx.y, b = blockIdx.z;
    int mode = g_mask_mode;

    // load Q tile (64x32) as float4 (512 float4, one per thread)
    {
        int qq = tid >> 3, d4 = (tid & 7) * 4;
        *(float4*)&sQ[qq * 36 + d4] =
            *(const float4*)&g_Qp[((b * SN + q0 + qq) * DM) + h * 32 + d4];
    }
    // load K (512x32) as float4
    #pragma unroll
    for (int t = 0; t < 8; t++) {
        int lin = tid + t * 512;
        int kk = lin >> 3, d4 = (lin & 7) * 4;
        *(float4*)&sKV[kk * 36 + d4] =
            *(const float4*)&g_Kp[((b * SN + kk) * DM) + h * 32 + d4];
    }
    __syncthreads();

    const float scale = 0.17677669529663687f; // 1/sqrt(32)
    int qg = tid >> 6;   // 0..7 : 8 q-rows each
    int kl = tid & 63;   // k columns kl + j*64

    float acc[8][8];
    #pragma unroll
    for (int i = 0; i < 8; i++)
        #pragma unroll
        for (int j = 0; j < 8; j++) acc[i][j] = 0.f;

    #pragma unroll
    for (int d = 0; d < 32; d += 4) {
        float4 qv[8];
        #pragma unroll
        for (int i = 0; i < 8; i++) qv[i] = *(const float4*)&sQ[(qg * 8 + i) * 36 + d];
        #pragma unroll
        for (int j = 0; j < 8; j++) {
            float4 kv = *(const float4*)&sKV[(kl + j * 64) * 36 + d];
            #pragma unroll
            for (int i = 0; i < 8; i++) {
                acc[i][j] += qv[i].x * kv.x;
                acc[i][j] += qv[i].y * kv.y;
                acc[i][j] += qv[i].z * kv.z;
                acc[i][j] += qv[i].w * kv.w;
            }
        }
    }

    int mrow0 = ((b * HN + h) * SN + q0) * SN;
    #pragma unroll
    for (int i = 0; i < 8; i++) {
        int q = qg * 8 + i;
        #pragma unroll
        for (int j = 0; j < 8; j++) {
            int k = kl + j * 64;
            int midx = mrow0 + q * SN + k;
            bool msk;
            if (mode == 0)      msk = ((const unsigned char*)mask)[midx] != 0;
            else if (mode == 1) msk = ((const int*)mask)[midx] != 0;
            else                msk = ((const float*)mask)[midx] != 0.0f;
            sS[q * 512 + k] = msk ? -1e9f : acc[i][j] * scale;
        }
    }
    __syncthreads();

    // reload sKV with V (512x32) — K no longer needed
    #pragma unroll
    for (int t = 0; t < 8; t++) {
        int lin = tid + t * 512;
        int kk = lin >> 3, d4 = (lin & 7) * 4;
        *(float4*)&sKV[kk * 36 + d4] =
            *(const float4*)&g_Vp[((b * SN + kk) * DM) + h * 32 + d4];
    }

    // exact softmax per row (16 warps x 4 rows), emit fp16 attn map
    int warp = tid >> 5, lane = tid & 31;
    #pragma unroll
    for (int rep = 0; rep < 4; rep++) {
        int r = warp * 4 + rep;
        float mx = -INFINITY;
        #pragma unroll
        for (int i = 0; i < 16; i++) mx = fmaxf(mx, sS[r * 512 + lane + i * 32]);
        #pragma unroll
        for (int o = 16; o; o >>= 1) mx = fmaxf(mx, __shfl_xor_sync(0xffffffffu, mx, o));
        float sum = 0.f;
        #pragma unroll
        for (int i = 0; i < 16; i++) {
            int c = lane + i * 32;
            float p = __expf(sS[r * 512 + c] - mx);
            sS[r * 512 + c] = p; sum += p;
        }
        #pragma unroll
        for (int o = 16; o; o >>= 1) sum += __shfl_xor_sync(0xffffffffu, sum, o);
        float inv = 1.0f / sum;
        __syncwarp();
        size_t base = (size_t)(((b * HN + h) * SN + q0 + r)) * SN;
        #pragma unroll
        for (int i = 0; i < 8; i++) {
            int c0 = lane * 2 + i * 64;
            float2 pv = *(float2*)&sS[r * 512 + c0];
            pv.x *= inv; pv.y *= inv;
            *(float2*)&sS[r * 512 + c0] = pv;
            *(__half2*)&g_attnH[base + c0] = __floats2half2_rn(pv.x, pv.y);
        }
    }
    __syncthreads();

    // context = P @ V : 16-way k-split, each thread 8q x 8v over 32 k
    int part = tid >> 5;          // 0..15
    int pos  = tid & 31;
    int qi = pos >> 2;            // 0..7 -> q rows qi*8+i
    int vj = pos & 3;             // 0..3 -> v cols vj*8+j
    float cacc[8][8];
    #pragma unroll
    for (int i = 0; i < 8; i++)
        #pragma unroll
        for (int j = 0; j < 8; j++) cacc[i][j] = 0.f;

    #pragma unroll
    for (int kc = 0; kc < 8; kc++) {
        int k0 = part * 32 + kc * 4;
        float4 pv4[8];
        #pragma unroll
        for (int i = 0; i < 8; i++)
            pv4[i] = *(const float4*)&sS[(qi * 8 + i) * 512 + k0];
        #pragma unroll
        for (int m = 0; m < 4; m++) {
            float4 va = *(const float4*)&sKV[(k0 + m) * 36 + vj * 8];
            float4 vb = *(const float4*)&sKV[(k0 + m) * 36 + vj * 8 + 4];
            #pragma unroll
            for (int i = 0; i < 8; i++) {
                float p = (m == 0) ? pv4[i].x : (m == 1) ? pv4[i].y : (m == 2) ? pv4[i].z : pv4[i].w;
                cacc[i][0] += p * va.x; cacc[i][1] += p * va.y;
                cacc[i][2] += p * va.z; cacc[i][3] += p * va.w;
                cacc[i][4] += p * vb.x; cacc[i][5] += p * vb.y;
                cacc[i][6] += p * vb.z; cacc[i][7] += p * vb.w;
            }
        }
    }
    __syncthreads();   // all P reads complete; sS reusable as partial buffer
    #pragma unroll
    for (int i = 0; i < 8; i++) {
        int o = part * 2048 + (qi * 8 + i) * 32 + vj * 8;
        *(float4*)&sS[o]     = make_float4(cacc[i][0], cacc[i][1], cacc[i][2], cacc[i][3]);
        *(float4*)&sS[o + 4] = make_float4(cacc[i][4], cacc[i][5], cacc[i][6], cacc[i][7]);
    }
    __syncthreads();
    {
        int o = tid * 4;
        float4 s = make_float4(0.f, 0.f, 0.f, 0.f);
        #pragma unroll
        for (int p = 0; p < 16; p++) {
            float4 pp = *(const float4*)&sS[p * 2048 + o];
            s.x += pp.x; s.y += pp.y; s.z += pp.z; s.w += pp.w;
        }
        int q = o >> 5, dv = o & 31;
        *(float4*)&g_ctx[(b * SN + q0 + q) * CTXW + h * 32 + dv] = s;
    }
}

// ---------------- context2 = matrix @ V2p, per batch ----------------
__global__ void __launch_bounds__(256) ctx2_kernel(const float* __restrict__ matrix)
{
    __shared__ float Ms[128][33];
    __shared__ float Vs[32][33];
    int tid = threadIdx.x;
    int r0 = blockIdx.x * 128, b = blockIdx.y;
    int cg = tid & 7, rg = tid >> 3;
    float acc[4][4];
    #pragma unroll
    for (int i = 0; i < 4; i++)
        #pragma unroll
        for (int j = 0; j < 4; j++) acc[i][j] = 0.f;

    for (int kt = 0; kt < 16; kt++) {
        int k0 = kt * 32;
        #pragma unroll
        for (int t = 0; t < 16; t++) {
            int idx = tid + t * 256; int rr = idx >> 5, kk = idx & 31;
            Ms[rr][kk] = matrix[(size_t)(b * SN + r0 + rr) * SN + k0 + kk];
        }
        #pragma unroll
        for (int t = 0; t < 4; t++) {
            int idx = tid + t * 256; int kk = idx >> 5, c = idx & 31;
            Vs[kk][c] = g_V2p[(b * SN + k0 + kk) * 32 + c];
        }
        __syncthreads();
        #pragma unroll 8
        for (int kk = 0; kk < 32; kk++) {
            float a[4], w[4];
            #pragma unroll
            for (int i = 0; i < 4; i++) a[i] = Ms[rg * 4 + i][kk];
            #pragma unroll
            for (int j = 0; j < 4; j++) w[j] = Vs[kk][cg * 4 + j];
            #pragma unroll
            for (int i = 0; i < 4; i++)
                #pragma unroll
                for (int j = 0; j < 4; j++)
                    acc[i][j] += a[i] * w[j];
        }
        __syncthreads();
    }
    #pragma unroll
    for (int i = 0; i < 4; i++)
        #pragma unroll
        for (int j = 0; j < 4; j++)
            g_ctx[(b * SN + r0 + rg * 4 + i) * CTXW + 256 + cg * 4 + j] = acc[i][j];
}

// ---------------- gate MLP + matrix_out (attn in fp16) ----------------
__global__ void __launch_bounds__(256) gate_kernel(
    const float* __restrict__ matrix,
    const float* __restrict__ fug, const float* __restrict__ fub,
    const float* __restrict__ w1, const float* __restrict__ b1,
    const float* __restrict__ w2, const float* __restrict__ b2,
    float* __restrict__ out)
{
    __shared__ float As[8][32][33];
    __shared__ float Mt[32][33];
    __shared__ float sw1[54], sb1[6], sw2[6], sg[9], sbv[9];
    __shared__ float sb2;
    int tid = threadIdx.x;
    int x0 = blockIdx.x * 32, y0 = blockIdx.y * 32, b = blockIdx.z;

    if (tid < 54) sw1[tid] = w1[tid];
    else if (tid < 60) sb1[tid - 54] = b1[tid - 54];
    else if (tid < 66) sw2[tid - 60] = w2[tid - 60];
    else if (tid < 75) sg[tid - 66]  = fug[tid - 66];
    else if (tid < 84) sbv[tid - 75] = fub[tid - 75];
    else if (tid == 84) sb2 = b2[0];

    #pragma unroll
    for (int h = 0; h < 8; h++)
        #pragma unroll
        for (int t = 0; t < 2; t++) {
            int idx = tid + t * 256;         // 0..511
            int yy = idx >> 4, xp = idx & 15;
            __half2 hv = *(const __half2*)&g_attnH[
                (size_t)((b * 8 + h) * SN + y0 + yy) * SN + x0 + xp * 2];
            float2 fv = __half22float2(hv);
            As[h][yy][xp * 2]     = fv.x;
            As[h][yy][xp * 2 + 1] = fv.y;
        }
    #pragma unroll
    for (int t = 0; t < 4; t++) {
        int idx = tid + t * 256; int yy = idx >> 5, xx = idx & 31;
        Mt[yy][xx] = matrix[(size_t)(b * SN + y0 + yy) * SN + x0 + xx];
    }
    __syncthreads();

    #pragma unroll
    for (int t = 0; t < 4; t++) {
        int idx = tid + t * 256; int xx = idx >> 5, yy = idx & 31;
        float v[9];
        v[0] = Mt[yy][xx];
        #pragma unroll
        for (int h = 0; h < 8; h++) v[1 + h] = As[h][yy][xx];
        float s = 0.f, ss = 0.f;
        #pragma unroll
        for (int c = 0; c < 9; c++) { s += v[c]; ss += v[c] * v[c]; }
        float mean = s * (1.0f / 9.0f);
        float var = ss * (1.0f / 9.0f) - mean * mean;
        float inv = rsqrtf(var + 1e-5f);
        float h1[6];
        #pragma unroll
        for (int j = 0; j < 6; j++) h1[j] = sb1[j];
        #pragma unroll
        for (int c = 0; c < 9; c++) {
            float xn = sg[c] * ((v[c] - mean) * inv) + sbv[c];
            #pragma unroll
            for (int j = 0; j < 6; j++) h1[j] += xn * sw1[c * 6 + j];
        }
        float z = sb2;
        #pragma unroll
        for (int j = 0; j < 6; j++) z += fmaxf(h1[j], 0.f) * sw2[j];
        float gval = 1.0f / (1.0f + __expf(-z));
        size_t oidx = (size_t)(b * SN + x0 + xx) * SN + y0 + yy;
        out[oidx] = matrix[oidx] * gval;
    }
}

// ---------------- final: out = LN(ctx[8192x288] @ Wfc[288x256]) ----------------
__global__ void __launch_bounds__(256) final_kernel(
    const float* __restrict__ Wfc,
    const float* __restrict__ lng, const float* __restrict__ lnb,
    float* __restrict__ out)
{
    __shared__ float sW[32 * 256];
    __shared__ float As[16][33];
    int tid = threadIdx.x;
    int row0 = blockIdx.x * 16;
    int tx = tid & 63, ty = tid >> 6;
    float acc[4][4];
    #pragma unroll
    for (int i = 0; i < 4; i++)
        #pragma unroll
        for (int j = 0; j < 4; j++) acc[i][j] = 0.f;

    for (int k0 = 0; k0 < CTXW; k0 += 32) {
        #pragma unroll
        for (int t = 0; t < 32; t++) {
            int idx = tid + t * 256;
            sW[idx] = Wfc[(size_t)(k0 + (idx >> 8)) * 256 + (idx & 255)];
        }
        #pragma unroll
        for (int t = 0; t < 2; t++) {
            int idx = tid + t * 256; int rr = idx >> 5, kk = idx & 31;
            As[rr][kk] = g_ctx[(size_t)(row0 + rr) * CTXW + k0 + kk];
        }
        __syncthreads();
        #pragma unroll 8
        for (int kk = 0; kk < 32; kk++) {
            float a[4], w[4];
            #pragma unroll
            for (int i = 0; i < 4; i++) a[i] = As[ty * 4 + i][kk];
            #pragma unroll
            for (int j = 0; j < 4; j++) w[j] = sW[kk * 256 + tx + 64 * j];
            #pragma unroll
            for (int i = 0; i < 4; i++)
                #pragma unroll
                for (int j = 0; j < 4; j++)
                    acc[i][j] += a[i] * w[j];
        }
        __syncthreads();
    }
    #pragma unroll
    for (int i = 0; i < 4; i++)
        #pragma unroll
        for (int j = 0; j < 4; j++)
            sW[(ty * 4 + i) * 256 + tx + 64 * j] = acc[i][j];
    __syncthreads();

    int warp = tid >> 5, lane = tid & 31;
    #pragma unroll
    for (int rep = 0; rep < 2; rep++) {
        int r = warp * 2 + rep;
        float s = 0.f, ss = 0.f;
        #pragma unroll
        for (int i = 0; i < 8; i++) {
            float v = sW[r * 256 + lane + i * 32];
            s += v; ss += v * v;
        }
        #pragma unroll
        for (int o = 16; o; o >>= 1) {
            s  += __shfl_xor_sync(0xffffffffu, s, o);
            ss += __shfl_xor_sync(0xffffffffu, ss, o);
        }
        float mean = s * (1.f / 256.f);
        float var = ss * (1.f / 256.f) - mean * mean;
        float inv = rsqrtf(var + 1e-5f);
        #pragma unroll
        for (int i = 0; i < 8; i++) {
            int c = lane + i * 32;
            float v = sW[r * 256 + c];
            out[(size_t)(row0 + r) * 256 + c] = lng[c] * ((v - mean) * inv) + lnb[c];
        }
    }
}

// ---------------- launch ----------------
extern "C" void kernel_launch(void* const* d_in, const int* in_sizes, int n_in,
                              void* d_out, int out_size)
{
    const float* inQ   = (const float*)d_in[0];
    const float* inK   = (const float*)d_in[1];
    const float* inV   = (const float*)d_in[2];
    const void*  mask  = d_in[3];
    const float* matrix= (const float*)d_in[4];
    const float* WQ    = (const float*)d_in[5];
    const float* WK    = (const float*)d_in[6];
    const float* WV    = (const float*)d_in[7];
    const float* WV2   = (const float*)d_in[8];
    const float* Wfc   = (const float*)d_in[9];
    const float* lng   = (const float*)d_in[10];
    const float* lnb   = (const float*)d_in[11];
    const float* fug   = (const float*)d_in[12];
    const float* fub   = (const float*)d_in[13];
    const float* w1    = (const float*)d_in[14];
    const float* b1    = (const float*)d_in[15];
    const float* w2    = (const float*)d_in[16];
    const float* b2    = (const float*)d_in[17];
    float* out = (float*)d_out;

    float *Qp, *Kp, *Vp;
    cudaGetSymbolAddress((void**)&Qp, g_Qp);
    cudaGetSymbolAddress((void**)&Kp, g_Kp);
    cudaGetSymbolAddress((void**)&Vp, g_Vp);

    const int ATTN_SMEM = (64 * 512 + 512 * 36 + 64 * 36) * 4; // 214016 B
    cudaFuncSetAttribute(attn_kernel, cudaFuncAttributeMaxDynamicSharedMemorySize, ATTN_SMEM);

    detect_mask_kernel<<<1, 256>>>((const unsigned int*)mask);

    qkv_kernel<<<dim3(2, 64, 3), 256>>>(inQ, inK, inV, WQ, WK, WV, Qp, Kp, Vp);
    v2_kernel<<<BN * SN / 8, 256>>>(inV, WV2);

    attn_kernel<<<dim3(SN / 64, HN, BN), 512, ATTN_SMEM>>>(mask);

    ctx2_kernel<<<dim3(SN / 128, BN), 256>>>(matrix);

    gate_kernel<<<dim3(SN / 32, SN / 32, BN), 256>>>(
        matrix, fug, fub, w1, b1, w2, b2, out + (size_t)BN * SN * DM);

    final_kernel<<<BN * SN / 16, 256>>>(Wfc, lng, lnb, out);
}